// round 10
// baseline (speedup 1.0000x reference)
#include <cuda_runtime.h>
#include <cuda_bf16.h>

// Factorization machine forward (see R0 comments).
// One warp per row; lane l owns factors [4l,4l+4) => one float4 per V row.
// R6 change: explicit depth-8 register ring buffer on the V gather so each
// warp holds 8 outstanding LDG.128s (prior build was MLP~2-3 at 34 regs,
// DRAM stuck at 57.6%).

#define FM_B 8192
#define FM_K 200
#define FM_WARPS 8
#define FM_PIPE 8   // ring depth; FM_K - FM_PIPE = 192 divisible by 8

__global__ __launch_bounds__(FM_WARPS * 32, 4)
void fm_kernel(const int* __restrict__ idx,
               const float* __restrict__ xv,
               const float* __restrict__ bv,
               const float* __restrict__ w,
               const float4* __restrict__ V4,   // V as [1e6][32] float4
               const float* __restrict__ bias,
               float* __restrict__ out)
{
    __shared__ int   sidx[FM_WARPS][FM_K];
    __shared__ float sx  [FM_WARPS][FM_K];

    const int warp = threadIdx.x >> 5;
    const int lane = threadIdx.x & 31;
    const int row  = blockIdx.x * FM_WARPS + warp;
    if (row >= FM_B) return;

    const int*   irow = idx + (long long)row * FM_K;
    const float* xrow = xv  + (long long)row * FM_K;
    const float* brow = bv  + (long long)row * FM_K;

    // Stage idx/x in smem; fold Xw (b*w gather, L2-resident table) and the
    // Xnorm denominator into lane-strided partials.
    float xw = 0.0f, xs = 0.0f;
    for (int k = lane; k < FM_K; k += 32) {
        int   id = irow[k];
        float x  = xrow[k];
        sidx[warp][k] = id;
        sx  [warp][k] = x;
        xs += x;
        xw += brow[k] * __ldg(&w[id]);
    }
    __syncwarp();

    float4 a1 = make_float4(0.f, 0.f, 0.f, 0.f);
    float4 a2 = make_float4(0.f, 0.f, 0.f, 0.f);

    // ---- software pipeline: depth-8 register ring of V row float4s ----
    float4 buf[FM_PIPE];
#pragma unroll
    for (int i = 0; i < FM_PIPE; i++)
        buf[i] = __ldg(&V4[(long long)sidx[warp][i] * 32 + lane]);

    int k = 0;
#pragma unroll 8
    for (; k < FM_K - FM_PIPE; k++) {            // 192 iters, 8 LDGs in flight
        const float4 v = buf[k & (FM_PIPE - 1)];
        buf[k & (FM_PIPE - 1)] =
            __ldg(&V4[(long long)sidx[warp][k + FM_PIPE] * 32 + lane]);
        const float x  = sx[warp][k];
        const float x2 = x * x;
        a1.x = fmaf(x, v.x, a1.x);
        a1.y = fmaf(x, v.y, a1.y);
        a1.z = fmaf(x, v.z, a1.z);
        a1.w = fmaf(x, v.w, a1.w);
        a2.x = fmaf(x2, v.x * v.x, a2.x);
        a2.y = fmaf(x2, v.y * v.y, a2.y);
        a2.z = fmaf(x2, v.z * v.z, a2.z);
        a2.w = fmaf(x2, v.w * v.w, a2.w);
    }
#pragma unroll
    for (; k < FM_K; k++) {                      // drain the ring
        const float4 v = buf[k & (FM_PIPE - 1)];
        const float x  = sx[warp][k];
        const float x2 = x * x;
        a1.x = fmaf(x, v.x, a1.x);
        a1.y = fmaf(x, v.y, a1.y);
        a1.z = fmaf(x, v.z, a1.z);
        a1.w = fmaf(x, v.w, a1.w);
        a2.x = fmaf(x2, v.x * v.x, a2.x);
        a2.y = fmaf(x2, v.y * v.y, a2.y);
        a2.z = fmaf(x2, v.z * v.z, a2.z);
        a2.w = fmaf(x2, v.w * v.w, a2.w);
    }

    // per-lane contribution to sum_f (XV^2 - X2V2)
    float p = (a1.x * a1.x - a2.x) + (a1.y * a1.y - a2.y)
            + (a1.z * a1.z - a2.z) + (a1.w * a1.w - a2.w);

#pragma unroll
    for (int off = 16; off > 0; off >>= 1) {
        p  += __shfl_xor_sync(0xffffffffu, p,  off);
        xw += __shfl_xor_sync(0xffffffffu, xw, off);
        xs += __shfl_xor_sync(0xffffffffu, xs, off);
    }

    if (lane == 0) {
        float logit = bias[0] + xw + 0.5f / xs * p;
        out[row] = 1.0f / (1.0f + __expf(-logit));
    }
}

extern "C" void kernel_launch(void* const* d_in, const int* in_sizes, int n_in,
                              void* d_out, int out_size)
{
    const int*    idx  = (const int*)   d_in[0];   // [B,K] int32
    const float*  xval = (const float*) d_in[1];   // [B,K]
    const float*  bval = (const float*) d_in[2];   // [B,K]
    const float*  w    = (const float*) d_in[3];   // [1e6,1]
    const float4* V4   = (const float4*)d_in[4];   // [1e6,128]
    const float*  bias = (const float*) d_in[5];   // [1]
    float* out = (float*)d_out;                    // [B]

    dim3 block(FM_WARPS * 32);
    dim3 grid(FM_B / FM_WARPS);
    fm_kernel<<<grid, block>>>(idx, xval, bval, w, V4, bias, out);
}

// round 12
// speedup vs baseline: 1.3599x; 1.3599x over previous
#include <cuda_runtime.h>
#include <cuda_bf16.h>

// Factorization machine forward.
// One warp per row; lane l owns factors [4l,4l+4) => one float4 per V row.
// R10: depth-4 register pipeline (R6's depth-8 ring regressed: SB-slot
// aliasing capped effective MLP at ~3.5 while occupancy fell 43->27 warps).
// Depth 4 fits the 6 scoreboard slots; launch_bounds(256,5) keeps ~40 warps.

#define FM_B 8192
#define FM_K 200
#define FM_WARPS 8
#define FM_PIPE 4   // FM_K - FM_PIPE = 196 = 49*4 -> unroll 4 stays aligned

__global__ __launch_bounds__(FM_WARPS * 32, 5)
void fm_kernel(const int* __restrict__ idx,
               const float* __restrict__ xv,
               const float* __restrict__ bv,
               const float* __restrict__ w,
               const float4* __restrict__ V4,   // V as [1e6][32] float4
               const float* __restrict__ bias,
               float* __restrict__ out)
{
    __shared__ int   sidx[FM_WARPS][FM_K];
    __shared__ float sx  [FM_WARPS][FM_K];

    const int warp = threadIdx.x >> 5;
    const int lane = threadIdx.x & 31;
    const int row  = blockIdx.x * FM_WARPS + warp;
    if (row >= FM_B) return;

    const int*   irow = idx + (long long)row * FM_K;
    const float* xrow = xv  + (long long)row * FM_K;
    const float* brow = bv  + (long long)row * FM_K;

    // Stage idx/x in smem; fold Xw (b*w gather, L2-resident 4MB table) and
    // the Xnorm denominator into lane-strided partials.
    float xw = 0.0f, xs = 0.0f;
    for (int k = lane; k < FM_K; k += 32) {
        int   id = irow[k];
        float x  = xrow[k];
        sidx[warp][k] = id;
        sx  [warp][k] = x;
        xs += x;
        xw += brow[k] * __ldg(&w[id]);
    }
    __syncwarp();

    float4 a1 = make_float4(0.f, 0.f, 0.f, 0.f);
    float4 a2 = make_float4(0.f, 0.f, 0.f, 0.f);

    // ---- depth-4 register pipeline on the V gather ----
    float4 buf[FM_PIPE];
#pragma unroll
    for (int i = 0; i < FM_PIPE; i++)
        buf[i] = __ldg(&V4[(long long)sidx[warp][i] * 32 + lane]);

    int k = 0;
#pragma unroll 4
    for (; k < FM_K - FM_PIPE; k++) {            // 196 iters, 4 LDGs in flight
        const float4 v = buf[k & (FM_PIPE - 1)];
        buf[k & (FM_PIPE - 1)] =
            __ldg(&V4[(long long)sidx[warp][k + FM_PIPE] * 32 + lane]);
        const float x  = sx[warp][k];
        const float x2 = x * x;
        a1.x = fmaf(x, v.x, a1.x);
        a1.y = fmaf(x, v.y, a1.y);
        a1.z = fmaf(x, v.z, a1.z);
        a1.w = fmaf(x, v.w, a1.w);
        a2.x = fmaf(x2, v.x * v.x, a2.x);
        a2.y = fmaf(x2, v.y * v.y, a2.y);
        a2.z = fmaf(x2, v.z * v.z, a2.z);
        a2.w = fmaf(x2, v.w * v.w, a2.w);
    }
#pragma unroll
    for (; k < FM_K; k++) {                      // drain (4 iters)
        const float4 v = buf[k & (FM_PIPE - 1)];
        const float x  = sx[warp][k];
        const float x2 = x * x;
        a1.x = fmaf(x, v.x, a1.x);
        a1.y = fmaf(x, v.y, a1.y);
        a1.z = fmaf(x, v.z, a1.z);
        a1.w = fmaf(x, v.w, a1.w);
        a2.x = fmaf(x2, v.x * v.x, a2.x);
        a2.y = fmaf(x2, v.y * v.y, a2.y);
        a2.z = fmaf(x2, v.z * v.z, a2.z);
        a2.w = fmaf(x2, v.w * v.w, a2.w);
    }

    // per-lane contribution to sum_f (XV^2 - X2V2)
    float p = (a1.x * a1.x - a2.x) + (a1.y * a1.y - a2.y)
            + (a1.z * a1.z - a2.z) + (a1.w * a1.w - a2.w);

#pragma unroll
    for (int off = 16; off > 0; off >>= 1) {
        p  += __shfl_xor_sync(0xffffffffu, p,  off);
        xw += __shfl_xor_sync(0xffffffffu, xw, off);
        xs += __shfl_xor_sync(0xffffffffu, xs, off);
    }

    if (lane == 0) {
        float logit = bias[0] + xw + 0.5f / xs * p;
        out[row] = 1.0f / (1.0f + __expf(-logit));
    }
}

extern "C" void kernel_launch(void* const* d_in, const int* in_sizes, int n_in,
                              void* d_out, int out_size)
{
    const int*    idx  = (const int*)   d_in[0];   // [B,K] int32
    const float*  xval = (const float*) d_in[1];   // [B,K]
    const float*  bval = (const float*) d_in[2];   // [B,K]
    const float*  w    = (const float*) d_in[3];   // [1e6,1]
    const float4* V4   = (const float4*)d_in[4];   // [1e6,128]
    const float*  bias = (const float*) d_in[5];   // [1]
    float* out = (float*)d_out;                    // [B]

    dim3 block(FM_WARPS * 32);
    dim3 grid(FM_B / FM_WARPS);
    fm_kernel<<<grid, block>>>(idx, xval, bval, w, V4, bias, out);
}